// round 12
// baseline (speedup 1.0000x reference)
#include <cuda_runtime.h>
#include <cuda_bf16.h>

// MiscTypeChecker: [B=8192, S=8192] int32 tokens in [0,8), scalar f32 output.
// Backward suffix scan per row with early exit (presence monotone; backward
// first-hit of '1' == last occurrence). Expected read ~4.5MB of 256MB.
//
// R10: 128 CTAs x 1024 threads (32 warps x RPW=2 = 64 rows/CTA), one CTA/SM,
// single wave. Minimizes CTA launch/drain machinery and tail atomics (128
// pairs). Per-warp MLP=3 (2 chunk LDG.128 + head) unchanged.

#define S_DIM 8192
#define TYPE_RANGE 8
#define RPW 2           // rows per warp
#define TPB 1024        // threads per block
#define WPB (TPB / 32)  // 32 warps
#define ROWS_PER_BLOCK (WPB * RPW)  // 64

__device__ float    g_partial = 0.0f;
__device__ unsigned g_done    = 0u;

__device__ __forceinline__ void red_add_relaxed_f32(float* p, float v) {
    asm volatile("red.relaxed.gpu.global.add.f32 [%0], %1;"
                 :: "l"(p), "f"(v) : "memory");
}
__device__ __forceinline__ unsigned atom_inc_release(unsigned* p) {
    unsigned old;
    asm volatile("atom.release.gpu.global.add.u32 %0, [%1], 1;"
                 : "=r"(old) : "l"(p) : "memory");
    return old;
}
__device__ __forceinline__ float ld_acquire_f32(const float* p) {
    float v;
    asm volatile("ld.acquire.gpu.global.f32 %0, [%1];"
                 : "=f"(v) : "l"(p) : "memory");
    return v;
}

__device__ __forceinline__ void stats4(const int4 v, int eb,
                                       unsigned& p_out, int& l_out) {
    // presence (reference clips to [0, TYPE_RANGE-1])
    const int cx = min(max(v.x, 0), TYPE_RANGE - 1);
    const int cy = min(max(v.y, 0), TYPE_RANGE - 1);
    const int cz = min(max(v.z, 0), TYPE_RANGE - 1);
    const int cw = min(max(v.w, 0), TYPE_RANGE - 1);
    p_out = (1u << cx) | (1u << cy) | (1u << cz) | (1u << cw);
    // highest position of token==1 in this thread's 4 elems
    int l = -1;
    if (v.x == 1) l = eb;
    if (v.y == 1) l = eb + 1;
    if (v.z == 1) l = eb + 2;
    if (v.w == 1) l = eb + 3;
    l_out = l;
}

__global__ void __launch_bounds__(TPB, 1)
mtc_fused_kernel(const int* __restrict__ mpt, float* __restrict__ out,
                 int B, int nblocks, int out_size) {
    __shared__ int bsum;
    if (threadIdx.x == 0) bsum = 0;
    if (blockIdx.x == 0) {          // defensive: zero any extra out elems
        for (int i = 1 + (int)threadIdx.x; i < out_size; i += (int)blockDim.x)
            out[i] = 0.0f;
    }
    __syncthreads();

    const int warp = threadIdx.x >> 5;
    const int lane = threadIdx.x & 31;
    const int row0 = (blockIdx.x * WPB + warp) * RPW;

    int result = 0;  // lane r (< RPW) accumulates row r's score

    if (row0 < B) {
        // ---- issue all loads up front: 2 chunk LDG.128 + head (MLP=3) ----
        const int* rp[RPW];
        int4 v[RPW];
        bool valid[RPW];
#pragma unroll
        for (int r = 0; r < RPW; r++) {
            const int row = row0 + r;
            valid[r] = (row < B);
            rp[r] = mpt + (long long)(valid[r] ? row : 0) * S_DIM;
            if (valid[r])
                v[r] = reinterpret_cast<const int4*>(rp[r] + S_DIM - 128)[lane];
        }
        // lane r loads row r's first two tokens (independent, overlaps above)
        int2 h = make_int2(0, 1);
        if (lane < RPW && (row0 + lane) < B)
            h = *reinterpret_cast<const int2*>(mpt + (long long)(row0 + lane) * S_DIM);

        // ---- process rows; loads already in flight / landed ----
#pragma unroll
        for (int r = 0; r < RPW; r++) {
            if (!valid[r]) break;   // warp-uniform

            unsigned p; int l;
            stats4(v[r], (S_DIM - 128) + lane * 4, p, l);
            unsigned pres = __reduce_or_sync(0xffffffffu, p);
            int last1 = __reduce_max_sync(0xffffffffu, l);

            if (!(pres == 0xFFu && last1 >= 0)) {
                // exact fallback: continue backward over the whole row
                for (int base = S_DIM - 256; base >= 0; base -= 128) {
                    const int4 w = reinterpret_cast<const int4*>(rp[r] + base)[lane];
                    unsigned p2; int l2;
                    stats4(w, base + lane * 4, p2, l2);
                    pres |= __reduce_or_sync(0xffffffffu, p2);
                    if (last1 < 0)
                        last1 = __reduce_max_sync(0xffffffffu, l2);
                    if (pres == 0xFFu && last1 >= 0) break;
                }
            }

            if (lane == r) {
                int rr = ((h.x != 0) + (h.y != 1)) * 4;
                const int miss = TYPE_RANGE - __popc(pres);
                rr += miss * miss;
                int rg4 = 6;
                if (last1 > 0 && last1 < S_DIM - 5) {
                    const int* q = rp[r] + last1;   // lines just fetched: L1 hits
                    rg4 = (q[1] != 2) + (q[2] != 4) + (q[3] != 5) +
                          (q[4] != 6) + (q[5] != 3);
                }
                result += rr + rg4;
            }
        }

        const int wsum = __reduce_add_sync(0xffffffffu, result);
        if (lane == 0 && wsum != 0) atomicAdd(&bsum, wsum);
    }

    __syncthreads();

    if (threadIdx.x == 0) {
        // Float accumulation exact: integer-valued, total < 2^24.
        red_add_relaxed_f32(&g_partial, (float)bsum);
        const unsigned prev = atom_inc_release(&g_done);
        if (prev == (unsigned)nblocks - 1u) {
            out[0] = ld_acquire_f32(&g_partial);   // single acquire chip-wide
            g_partial = 0.0f;                      // reset for next replay
            g_done = 0u;
        }
    }
}

extern "C" void kernel_launch(void* const* d_in, const int* in_sizes, int n_in,
                              void* d_out, int out_size) {
    // Token matrix = largest input (type_range may arrive as a scalar input).
    int big = 0;
    for (int i = 1; i < n_in; i++)
        if (in_sizes[i] > in_sizes[big]) big = i;

    const int* mpt = (const int*)d_in[big];
    float* out = (float*)d_out;
    const int B = in_sizes[big] / S_DIM;
    const int nblocks = (B + ROWS_PER_BLOCK - 1) / ROWS_PER_BLOCK;  // 128

    mtc_fused_kernel<<<nblocks, TPB>>>(mpt, out, B, nblocks, out_size);
}

// round 14
// speedup vs baseline: 1.0590x; 1.0590x over previous
#include <cuda_runtime.h>
#include <cuda_bf16.h>

// MiscTypeChecker: [B=8192, S=8192] int32 tokens in [0,8), scalar f32 output.
// Backward suffix scan per row with early exit (presence monotone; backward
// first-hit of '1' == last occurrence). 64-elem (256B) suffix chunk resolves
// ~99.85% of rows; exact full-row fallback covers the rest. ~2.3MB read.
//
// R13: best-total shape (RPW=4, 256thr, grid=256, single wave) + int2 chunks
// to shorten the L2-warm critical path. Tail: relaxed partial + release
// counter, one acquire chip-wide (last block), reset for graph replay.

#define S_DIM 8192
#define TYPE_RANGE 8
#define RPW 4          // rows per warp
#define WPB 8          // warps per block (256 threads)
#define CHUNK 64       // elems per suffix chunk (32 lanes x int2)

__device__ float    g_partial = 0.0f;
__device__ unsigned g_done    = 0u;

__device__ __forceinline__ void red_add_relaxed_f32(float* p, float v) {
    asm volatile("red.relaxed.gpu.global.add.f32 [%0], %1;"
                 :: "l"(p), "f"(v) : "memory");
}
__device__ __forceinline__ unsigned atom_inc_release(unsigned* p) {
    unsigned old;
    asm volatile("atom.release.gpu.global.add.u32 %0, [%1], 1;"
                 : "=r"(old) : "l"(p) : "memory");
    return old;
}
__device__ __forceinline__ float ld_acquire_f32(const float* p) {
    float v;
    asm volatile("ld.acquire.gpu.global.f32 %0, [%1];"
                 : "=f"(v) : "l"(p) : "memory");
    return v;
}

__device__ __forceinline__ void stats2(const int2 v, int eb,
                                       unsigned& p_out, int& l_out) {
    // presence (reference clips to [0, TYPE_RANGE-1])
    const int cx = min(max(v.x, 0), TYPE_RANGE - 1);
    const int cy = min(max(v.y, 0), TYPE_RANGE - 1);
    p_out = (1u << cx) | (1u << cy);
    // highest position of token==1 in this thread's 2 elems
    int l = -1;
    if (v.x == 1) l = eb;
    if (v.y == 1) l = eb + 1;
    l_out = l;
}

__global__ void __launch_bounds__(256)
mtc_fused_kernel(const int* __restrict__ mpt, float* __restrict__ out,
                 int B, int nblocks, int out_size) {
    __shared__ int bsum;
    if (threadIdx.x == 0) bsum = 0;
    if (blockIdx.x == 0) {          // defensive: zero any extra out elems
        for (int i = 1 + (int)threadIdx.x; i < out_size; i += (int)blockDim.x)
            out[i] = 0.0f;
    }
    __syncthreads();

    const int warp = threadIdx.x >> 5;
    const int lane = threadIdx.x & 31;
    const int row0 = (blockIdx.x * WPB + warp) * RPW;

    int result = 0;  // lane r (< RPW) accumulates row r's score

    if (row0 < B) {
        // ---- front-batch all loads: RPW chunk LDG.64 + head (MLP=5) ----
        const int* rp[RPW];
        int2 v[RPW];
        bool valid[RPW];
#pragma unroll
        for (int r = 0; r < RPW; r++) {
            const int row = row0 + r;
            valid[r] = (row < B);
            rp[r] = mpt + (long long)(valid[r] ? row : 0) * S_DIM;
            if (valid[r])
                v[r] = reinterpret_cast<const int2*>(rp[r] + S_DIM - CHUNK)[lane];
        }
        // lane r loads row r's first two tokens (independent, overlaps above)
        int2 h = make_int2(0, 1);
        if (lane < RPW && (row0 + lane) < B)
            h = *reinterpret_cast<const int2*>(mpt + (long long)(row0 + lane) * S_DIM);

        // ---- process rows; loads already in flight / landed ----
#pragma unroll
        for (int r = 0; r < RPW; r++) {
            if (!valid[r]) break;   // warp-uniform

            unsigned p; int l;
            stats2(v[r], (S_DIM - CHUNK) + lane * 2, p, l);
            unsigned pres = __reduce_or_sync(0xffffffffu, p);
            int last1 = __reduce_max_sync(0xffffffffu, l);

            if (!(pres == 0xFFu && last1 >= 0)) {
                // exact fallback: continue backward over the whole row
                for (int base = S_DIM - 2 * CHUNK; base >= 0; base -= CHUNK) {
                    const int2 w = reinterpret_cast<const int2*>(rp[r] + base)[lane];
                    unsigned p2; int l2;
                    stats2(w, base + lane * 2, p2, l2);
                    pres |= __reduce_or_sync(0xffffffffu, p2);
                    if (last1 < 0)
                        last1 = __reduce_max_sync(0xffffffffu, l2);
                    if (pres == 0xFFu && last1 >= 0) break;
                }
            }

            if (lane == r) {
                int rr = ((h.x != 0) + (h.y != 1)) * 4;
                const int miss = TYPE_RANGE - __popc(pres);
                rr += miss * miss;
                int rg4 = 6;
                if (last1 > 0 && last1 < S_DIM - 5) {
                    const int* q = rp[r] + last1;   // lines just fetched: L1 hits
                    rg4 = (q[1] != 2) + (q[2] != 4) + (q[3] != 5) +
                          (q[4] != 6) + (q[5] != 3);
                }
                result += rr + rg4;
            }
        }

        const int wsum = __reduce_add_sync(0xffffffffu, result);
        if (lane == 0 && wsum != 0) atomicAdd(&bsum, wsum);
    }

    __syncthreads();

    if (threadIdx.x == 0) {
        // Float accumulation exact: integer-valued, total < 2^24.
        red_add_relaxed_f32(&g_partial, (float)bsum);
        const unsigned prev = atom_inc_release(&g_done);
        if (prev == (unsigned)nblocks - 1u) {
            out[0] = ld_acquire_f32(&g_partial);   // single acquire chip-wide
            g_partial = 0.0f;                      // reset for next replay
            g_done = 0u;
        }
    }
}

extern "C" void kernel_launch(void* const* d_in, const int* in_sizes, int n_in,
                              void* d_out, int out_size) {
    // Token matrix = largest input (type_range may arrive as a scalar input).
    int big = 0;
    for (int i = 1; i < n_in; i++)
        if (in_sizes[i] > in_sizes[big]) big = i;

    const int* mpt = (const int*)d_in[big];
    float* out = (float*)d_out;
    const int B = in_sizes[big] / S_DIM;
    const int nblocks = (B + RPW * WPB - 1) / (RPW * WPB);   // 256 for B=8192

    mtc_fused_kernel<<<nblocks, 256>>>(mpt, out, B, nblocks, out_size);
}